// round 6
// baseline (speedup 1.0000x reference)
#include <cuda_runtime.h>
#include <math.h>

#define FRAME_LEN 400
#define HOP 160
#define FFT_LEN 512
#define NBINS 257
#define NMEL 80
#define PREEMPH 0.97f
#define MEL_FLOOR 1.192092955078125e-07f
#define ABLOCKS 592
#define WCAP 1024
#define NTASK 640            // 8 frames x 80 bins

// ---- device scratch ----
#define MAX_FRAMES 60000
__device__ float  g_mel [MAX_FRAMES * NMEL];
__device__ float2 g_twid[512];
__device__ float  g_psum[ABLOCKS * NTASK];
__device__ float  g_psq [ABLOCKS * NTASK];
__device__ float  g_mean[NMEL];
__device__ float  g_istd[NMEL];
__device__ int    g_klo[NMEL];
__device__ int    g_wid[NMEL];
__device__ int    g_off[NMEL];
__device__ float  g_wts[WCAP];

// ---------------------------------------------------------------------------
// Combined init: twiddles (512 threads) + filterbank compaction.
__global__ void init_kernel(const float* __restrict__ fb) {
    __shared__ int wid_sh[NMEL];
    __shared__ int off_sh[NMEL];
    const int tid = threadIdx.x;

    {   // twiddles
        double a = -2.0 * 3.14159265358979323846 * (double)tid / 512.0;
        g_twid[tid] = make_float2((float)cos(a), (float)sin(a));
    }

    if (tid < NMEL) {
        int lo = -1, hi = -2;
        for (int k = 0; k < NBINS; ++k)
            if (fb[k * NMEL + tid] != 0.0f) { if (lo < 0) lo = k; hi = k; }
        int w = hi - lo + 1;
        if (w < 0) w = 0;
        g_klo[tid] = (lo < 0) ? 0 : lo;
        wid_sh[tid] = w;
    }
    __syncthreads();
    if (tid == 0) {
        int off = 0;
        for (int i = 0; i < NMEL; ++i) {
            int w = wid_sh[i];
            if (off + w > WCAP) w = WCAP - off;
            if (w < 0) w = 0;
            wid_sh[i] = w;
            off_sh[i] = off;
            off += w;
        }
    }
    __syncthreads();
    if (tid < NMEL) {
        int off = off_sh[tid], lo = g_klo[tid], w = wid_sh[tid];
        g_wid[tid] = w;
        g_off[tid] = off;
        for (int i = 0; i < w; ++i)
            g_wts[off + i] = fb[(lo + i) * NMEL + tid];
    }
}

// ---------------------------------------------------------------------------
#define PHYS8(i) ((i) + ((i) >> 3))
#define BUF 576                       // 512 + 64 pad (float2 elems)
#define SPEC_LD 260
#define STAGE_LEN 1520                // 7*HOP + FRAME_LEN

#define FFT2(ar,ai,br,bi) { float tr_=ar, ti_=ai; ar=tr_+br; ai=ti_+bi; br=tr_-br; bi=ti_-bi; }
#define CMUL(xr,xi,wr,wi) { float tr_=xr; xr=tr_*(wr)-xi*(wi); xi=tr_*(wi)+xi*(wr); }
#define RSQ2 0.70710678118654752440f

// 8-pt DIF DFT; output v[m] = X[brev3(m)], brev3 = {0,4,2,6,1,5,3,7}
__device__ __forceinline__ void fft8(float* vr, float* vi) {
    FFT2(vr[0], vi[0], vr[4], vi[4]);
    FFT2(vr[1], vi[1], vr[5], vi[5]);
    FFT2(vr[2], vi[2], vr[6], vi[6]);
    FFT2(vr[3], vi[3], vr[7], vi[7]);
    CMUL(vr[5], vi[5],  RSQ2, -RSQ2);
    CMUL(vr[6], vi[6],  0.0f, -1.0f);
    CMUL(vr[7], vi[7], -RSQ2, -RSQ2);
    FFT2(vr[0], vi[0], vr[2], vi[2]);
    FFT2(vr[1], vi[1], vr[3], vi[3]);
    FFT2(vr[4], vi[4], vr[6], vi[6]);
    FFT2(vr[5], vi[5], vr[7], vi[7]);
    CMUL(vr[3], vi[3], 0.0f, -1.0f);
    CMUL(vr[7], vi[7], 0.0f, -1.0f);
    FFT2(vr[0], vi[0], vr[1], vi[1]);
    FFT2(vr[2], vi[2], vr[3], vi[3]);
    FFT2(vr[4], vi[4], vr[5], vi[5]);
    FFT2(vr[6], vi[6], vr[7], vi[7]);
}

__global__ __launch_bounds__(256, 4)
void fused_kernel(const float* __restrict__ wav,
                  const float* __restrict__ window,
                  int num_frames, int T) {
    extern __shared__ __align__(16) char dyn[];
    float2 (*A)[BUF] = (float2(*)[BUF])dyn;                 // 18432 B
    float2 (*B)[BUF] = (float2(*)[BUF])(dyn + 4 * BUF * 8); // 18432 B
    float* spec = (float*)A;             // alias: spec[8][SPEC_LD] in A bytes
    float* Wb   = (float*)B;             // alias: wav stage [STAGE_LEN] in B bytes

    __shared__ float  win_s[FRAME_LEN];
    __shared__ float2 tw[512];
    __shared__ float  wts_s[WCAP];
    __shared__ int    klo_s[NMEL], wid_s[NMEL], off_s[NMEL];

    const int tid  = threadIdx.x;
    const int warp = tid >> 5;
    const int lane = tid & 31;
    const int g = tid >> 6;       // FFT buffer 0..3
    const int j = tid & 63;       // butterfly lane

    for (int i = tid; i < FRAME_LEN; i += 256) win_s[i] = window[i];
    tw[tid] = g_twid[tid];
    tw[tid + 256] = g_twid[tid + 256];
    if (tid < NMEL) {
        klo_s[tid] = g_klo[tid];
        wid_s[tid] = g_wid[tid];
        off_s[tid] = g_off[tid];
    }
    __syncthreads();
    {
        int tot = off_s[NMEL - 1] + wid_s[NMEL - 1];
        for (int i = tid; i < tot; i += 256) wts_s[i] = g_wts[i];
    }
    // wts_s reads are separated from these writes by the barriers below

    float acc_s[3] = {0.f, 0.f, 0.f};
    float acc_q[3] = {0.f, 0.f, 0.f};
    const int BRv[8] = {0, 4, 2, 6, 1, 5, 3, 7};

    for (int base = blockIdx.x * 8; base < num_frames; base += gridDim.x * 8) {
        const long long s0 = (long long)base * HOP;

        // ---- phase 0: stage wav span into smem (float4 coalesced)
        for (int i = tid * 4; i < STAGE_LEN; i += 1024) {
            float4 v;
            if (s0 + i + 3 < T) {
                v = *(const float4*)(wav + s0 + i);
            } else {
                v.x = (s0 + i     < T) ? wav[s0 + i]     : 0.0f;
                v.y = (s0 + i + 1 < T) ? wav[s0 + i + 1] : 0.0f;
                v.z = (s0 + i + 2 < T) ? wav[s0 + i + 2] : 0.0f;
                v.w = (s0 + i + 3 < T) ? wav[s0 + i + 3] : 0.0f;
            }
            *(float4*)&Wb[i] = v;
        }
        __syncthreads();

        // ---- phase 1: mean + preemph + window, scatter into A (natural order)
        {
            const int f     = base + warp;
            const bool valid = (f < num_frames);
            const int buf   = warp >> 1;
            const int comp  = warp & 1;          // 0 -> re(.x), 1 -> im(.y)
            const int o     = warp * HOP;

            float m = 0.0f;
            if (valid) {
                float s = 0.0f;
                for (int n = lane; n < FRAME_LEN; n += 32) s += Wb[o + n];
                #pragma unroll
                for (int t = 16; t > 0; t >>= 1) s += __shfl_xor_sync(0xffffffffu, s, t);
                m = s * (32768.0f / FRAME_LEN);
            }
            const float mc = m * (1.0f - PREEMPH);

            float* dstf = (float*)&A[buf][0];
            for (int n = lane; n < FFT_LEN; n += 32) {
                float v = 0.0f;
                if (valid && n < FRAME_LEN) {
                    if (n == 0) v = (Wb[o] * 32768.0f - m) * (1.0f - PREEMPH);
                    else        v = (Wb[o + n] - PREEMPH * Wb[o + n - 1]) * 32768.0f - mc;
                    v *= win_s[n];
                }
                dstf[PHYS8(n) * 2 + comp] = v;
            }
        }
        __syncthreads();

        float vr[8], vi[8];

        // ---- pass 1: A -> B  (Ns=1, no twiddle), write 8j + brev(m)
        #pragma unroll
        for (int r = 0; r < 8; ++r) {
            float2 z = A[g][PHYS8(j + (r << 6))];
            vr[r] = z.x; vi[r] = z.y;
        }
        fft8(vr, vi);
        {
            const int d = j << 3;
            #pragma unroll
            for (int m = 0; m < 8; ++m)
                B[g][PHYS8(d + BRv[m])] = make_float2(vr[m], vi[m]);
        }
        __syncthreads();

        // ---- pass 2: B -> A  (Ns=8), tw idx 8*r*q, write (j>>3)*64+q + 8*brev
        {
            const int q = j & 7;
            #pragma unroll
            for (int r = 0; r < 8; ++r) {
                float2 z = B[g][PHYS8(j + (r << 6))];
                vr[r] = z.x; vi[r] = z.y;
                if (r) {
                    float2 w = tw[(r * q) << 3];
                    CMUL(vr[r], vi[r], w.x, w.y);
                }
            }
            fft8(vr, vi);
            const int d = ((j >> 3) << 6) + q;
            #pragma unroll
            for (int m = 0; m < 8; ++m)
                A[g][PHYS8(d + (BRv[m] << 3))] = make_float2(vr[m], vi[m]);
        }
        __syncthreads();

        // ---- pass 3: A -> B  (Ns=64), tw idx r*j, write j + 64*brev
        {
            #pragma unroll
            for (int r = 0; r < 8; ++r) {
                float2 z = A[g][PHYS8(j + (r << 6))];
                vr[r] = z.x; vi[r] = z.y;
                if (r) {
                    float2 w = tw[r * j];
                    CMUL(vr[r], vi[r], w.x, w.y);
                }
            }
            fft8(vr, vi);
            #pragma unroll
            for (int m = 0; m < 8; ++m)
                B[g][PHYS8(j + (BRv[m] << 6))] = make_float2(vr[m], vi[m]);
        }
        __syncthreads();

        // ---- unpack B -> power spectra in spec (A bytes); Z = A + iB
        for (int k = j; k < NBINS; k += 64) {
            const int mm = (FFT_LEN - k) & (FFT_LEN - 1);
            float2 z1 = B[g][PHYS8(k)];
            float2 z2 = B[g][PHYS8(mm)];
            float ar = z1.x + z2.x, ai = z1.y - z2.y;
            float br = z1.y + z2.y, bi = z1.x - z2.x;
            spec[(2 * g)     * SPEC_LD + k] = 0.25f * (ar * ar + ai * ai);
            spec[(2 * g + 1) * SPEC_LD + k] = 0.25f * (br * br + bi * bi);
        }
        __syncthreads();

        // ---- sparse mel + log + per-thread stats (fixed slots, deterministic)
        #pragma unroll
        for (int slot = 0; slot < 3; ++slot) {
            int t = tid + slot * 256;
            if (t < NTASK) {
                int fr = t / NMEL;
                int b  = t - fr * NMEL;
                int f2 = base + fr;
                float lv = 0.0f;
                if (f2 < num_frames) {
                    int lo = klo_s[b], w = wid_s[b], off = off_s[b];
                    float acc = 0.0f;
                    for (int i = 0; i < w; ++i)
                        acc = fmaf(spec[fr * SPEC_LD + lo + i], wts_s[off + i], acc);
                    lv = logf(fmaxf(acc, MEL_FLOOR));
                    g_mel[(long long)f2 * NMEL + b] = lv;
                }
                acc_s[slot] += lv;
                acc_q[slot] += lv * lv;
            }
        }
        __syncthreads();   // protect spec(A) / Wb(B) before next iteration
    }

    #pragma unroll
    for (int slot = 0; slot < 3; ++slot) {
        int t = tid + slot * 256;
        if (t < NTASK) {
            g_psum[blockIdx.x * NTASK + t] = acc_s[slot];
            g_psq [blockIdx.x * NTASK + t] = acc_q[slot];
        }
    }
}

// ---------------------------------------------------------------------------
// One block per mel bin: fp64 accumulate over 592 blocks x 8 fr-slots,
// deterministic shared tree.
__global__ void reduce2_kernel(int num_frames) {
    __shared__ double sh_s[256], sh_q[256];
    const int b = blockIdx.x;
    const int t = threadIdx.x;
    double s = 0.0, q = 0.0;
    for (int p = t; p < ABLOCKS * 8; p += 256) {
        int i  = p >> 3;
        int fr = p & 7;
        int a  = i * NTASK + fr * NMEL + b;
        s += (double)g_psum[a];
        q += (double)g_psq [a];
    }
    sh_s[t] = s; sh_q[t] = q;
    __syncthreads();
    #pragma unroll
    for (int o = 128; o > 0; o >>= 1) {
        if (t < o) { sh_s[t] += sh_s[t + o]; sh_q[t] += sh_q[t + o]; }
        __syncthreads();
    }
    if (t == 0) {
        double F = (double)num_frames;
        double mean = sh_s[0] / F;
        double var  = (sh_q[0] - F * mean * mean) / (F - 1.0);
        if (var < 0.0) var = 0.0;
        g_mean[b] = (float)mean;
        g_istd[b] = (float)(1.0 / sqrt(var + 1e-7));
    }
}

// ---------------------------------------------------------------------------
__global__ void normalize_kernel(float4* __restrict__ out, int n4) {
    __shared__ float mean_s[NMEL], istd_s[NMEL];
    if (threadIdx.x < NMEL) {
        mean_s[threadIdx.x] = g_mean[threadIdx.x];
        istd_s[threadIdx.x] = g_istd[threadIdx.x];
    }
    __syncthreads();
    const float4* mel4 = (const float4*)g_mel;
    for (int i = blockIdx.x * blockDim.x + threadIdx.x; i < n4;
         i += gridDim.x * blockDim.x) {
        int b = (i % 20) * 4;
        float4 v = mel4[i];
        float4 r;
        r.x = (v.x - mean_s[b    ]) * istd_s[b    ];
        r.y = (v.y - mean_s[b + 1]) * istd_s[b + 1];
        r.z = (v.z - mean_s[b + 2]) * istd_s[b + 2];
        r.w = (v.w - mean_s[b + 3]) * istd_s[b + 3];
        out[i] = r;
    }
}

// ---------------------------------------------------------------------------
extern "C" void kernel_launch(void* const* d_in, const int* in_sizes, int n_in,
                              void* d_out, int out_size) {
    const float* wav = (const float*)d_in[0];
    const float* fb  = (const float*)d_in[1];
    const float* win = (const float*)d_in[2];
    float* out = (float*)d_out;

    int T = in_sizes[0];
    int F = 1 + (T - FRAME_LEN) / HOP;
    if (F > MAX_FRAMES) F = MAX_FRAMES;

    const int dynB = 2 * 4 * BUF * 8;   // two float2[4][BUF] buffers = 36864 B

    init_kernel<<<1, 512>>>(fb);
    fused_kernel<<<ABLOCKS, 256, dynB>>>(wav, win, F, T);
    reduce2_kernel<<<NMEL, 256>>>(F);
    normalize_kernel<<<1024, 256>>>((float4*)out, F * NMEL / 4);
}

// round 8
// speedup vs baseline: 1.0329x; 1.0329x over previous
#include <cuda_runtime.h>
#include <math.h>

#define FRAME_LEN 400
#define HOP 160
#define FFT_LEN 512
#define NBINS 257
#define NMEL 80
#define PREEMPH 0.97f
#define MEL_FLOOR 1.192092955078125e-07f
#define ABLOCKS 592
#define WCAP 640
#define PB 768               // per-block stat slots: 4 groups x 3 slots x 64

// ---- device scratch ----
#define MAX_FRAMES 60000
__device__ float  g_mel [MAX_FRAMES * NMEL];
__device__ float2 g_twid[512];
__device__ float  g_psum[ABLOCKS * PB];
__device__ float  g_psq [ABLOCKS * PB];
__device__ float  g_mean[NMEL];
__device__ float  g_istd[NMEL];
__device__ int    g_klo[NMEL];
__device__ int    g_wid[NMEL];
__device__ int    g_off[NMEL];
__device__ float  g_wts[WCAP];

// ---------------------------------------------------------------------------
__global__ void init_kernel(const float* __restrict__ fb) {
    __shared__ int wid_sh[NMEL];
    __shared__ int off_sh[NMEL];
    const int tid = threadIdx.x;

    {
        double a = -2.0 * 3.14159265358979323846 * (double)tid / 512.0;
        g_twid[tid] = make_float2((float)cos(a), (float)sin(a));
    }

    if (tid < NMEL) {
        int lo = -1, hi = -2;
        for (int k = 0; k < NBINS; ++k)
            if (fb[k * NMEL + tid] != 0.0f) { if (lo < 0) lo = k; hi = k; }
        int w = hi - lo + 1;
        if (w < 0) w = 0;
        g_klo[tid] = (lo < 0) ? 0 : lo;
        wid_sh[tid] = w;
    }
    __syncthreads();
    if (tid == 0) {
        int off = 0;
        for (int i = 0; i < NMEL; ++i) {
            int w = wid_sh[i];
            if (off + w > WCAP) w = WCAP - off;
            if (w < 0) w = 0;
            wid_sh[i] = w;
            off_sh[i] = off;
            off += w;
        }
    }
    __syncthreads();
    if (tid < NMEL) {
        int off = off_sh[tid], lo = g_klo[tid], w = wid_sh[tid];
        g_wid[tid] = w;
        g_off[tid] = off;
        for (int i = 0; i < w; ++i)
            g_wts[off + i] = fb[(lo + i) * NMEL + tid];
    }
}

// ---------------------------------------------------------------------------
#define PHYS8(i) ((i) + ((i) >> 3))
#define BUF 576                 // float2 elems per group buffer
#define SPEC_LD 272
#define GSPAN 560               // HOP + FRAME_LEN  (2-frame group span)

#define FFT2(ar,ai,br,bi) { float tr_=ar, ti_=ai; ar=tr_+br; ai=ti_+bi; br=tr_-br; bi=ti_-bi; }
#define CMUL(xr,xi,wr,wi) { float tr_=xr; xr=tr_*(wr)-xi*(wi); xi=tr_*(wi)+xi*(wr); }
#define RSQ2 0.70710678118654752440f
// group-scoped barrier: 64 threads, ids 1..4
#define GBAR() asm volatile("bar.sync %0, 64;" :: "r"(1 + g) : "memory")

__device__ __forceinline__ void fft8(float* vr, float* vi) {
    FFT2(vr[0], vi[0], vr[4], vi[4]);
    FFT2(vr[1], vi[1], vr[5], vi[5]);
    FFT2(vr[2], vi[2], vr[6], vi[6]);
    FFT2(vr[3], vi[3], vr[7], vi[7]);
    CMUL(vr[5], vi[5],  RSQ2, -RSQ2);
    CMUL(vr[6], vi[6],  0.0f, -1.0f);
    CMUL(vr[7], vi[7], -RSQ2, -RSQ2);
    FFT2(vr[0], vi[0], vr[2], vi[2]);
    FFT2(vr[1], vi[1], vr[3], vi[3]);
    FFT2(vr[4], vi[4], vr[6], vi[6]);
    FFT2(vr[5], vi[5], vr[7], vi[7]);
    CMUL(vr[3], vi[3], 0.0f, -1.0f);
    CMUL(vr[7], vi[7], 0.0f, -1.0f);
    FFT2(vr[0], vi[0], vr[1], vi[1]);
    FFT2(vr[2], vi[2], vr[3], vi[3]);
    FFT2(vr[4], vi[4], vr[5], vi[5]);
    FFT2(vr[6], vi[6], vr[7], vi[7]);
}

__global__ __launch_bounds__(256, 4)
void fused_kernel(const float* __restrict__ wav,
                  const float* __restrict__ window,
                  int num_frames, int T) {
    extern __shared__ __align__(16) char dyn[];
    float2 (*A)[BUF] = (float2(*)[BUF])dyn;
    float2 (*B)[BUF] = (float2(*)[BUF])(dyn + 4 * BUF * 8);

    __shared__ float  win_s[FRAME_LEN];
    __shared__ float2 tw[512];
    __shared__ float  wts_s[WCAP];
    __shared__ int    klo_s[NMEL], wid_s[NMEL], off_s[NMEL];

    const int tid  = threadIdx.x;
    const int g    = tid >> 6;      // independent 64-thread group
    const int j    = tid & 63;      // lane within group
    const int w    = j >> 5;        // local warp (0: re, 1: im)
    const int lane = j & 31;

    // group-local aliases
    float* stage = (float*)&B[g][0];          // wav stage   (dead before pass1 writes B)
    float* specg = (float*)&A[g][0];          // spec[2][SPEC_LD] (dead before phase1 writes A)
    float* dstf  = (float*)&A[g][0];          // scatter target (component-interleaved)

    for (int i = tid; i < FRAME_LEN; i += 256) win_s[i] = window[i];
    tw[tid] = g_twid[tid];
    tw[tid + 256] = g_twid[tid + 256];
    if (tid < NMEL) {
        klo_s[tid] = g_klo[tid];
        wid_s[tid] = g_wid[tid];
        off_s[tid] = g_off[tid];
    }
    __syncthreads();
    {
        int tot = off_s[NMEL - 1] + wid_s[NMEL - 1];
        for (int i = tid; i < tot; i += 256) wts_s[i] = g_wts[i];
    }
    __syncthreads();   // all read-only shared tables ready

    float acc_s[3] = {0.f, 0.f, 0.f};
    float acc_q[3] = {0.f, 0.f, 0.f};
    const int BRv[8] = {0, 4, 2, 6, 1, 5, 3, 7};

    for (int base = blockIdx.x * 8; base < num_frames; base += gridDim.x * 8) {
        const int  fg = base + 2 * g;                 // group's first frame
        const long long s0 = (long long)fg * HOP;

        // ---- phase 0: group stages its 560-sample span (float4)
        for (int i = j * 4; i < GSPAN; i += 256) {
            float4 v;
            if (s0 + i + 3 < T) {
                v = *(const float4*)(wav + s0 + i);
            } else {
                v.x = (s0 + i     < T) ? wav[s0 + i]     : 0.0f;
                v.y = (s0 + i + 1 < T) ? wav[s0 + i + 1] : 0.0f;
                v.z = (s0 + i + 2 < T) ? wav[s0 + i + 2] : 0.0f;
                v.w = (s0 + i + 3 < T) ? wav[s0 + i + 3] : 0.0f;
            }
            *(float4*)&stage[i] = v;
        }
        GBAR();

        // ---- phase 1: mean + preemph + window -> scatter into A (natural order)
        {
            const int  f     = fg + w;
            const bool valid = (f < num_frames);
            const int  o     = w * HOP;

            float m = 0.0f;
            if (valid) {
                float s = 0.0f;
                for (int n = lane; n < FRAME_LEN; n += 32) s += stage[o + n];
                #pragma unroll
                for (int t = 16; t > 0; t >>= 1) s += __shfl_xor_sync(0xffffffffu, s, t);
                m = s * (32768.0f / FRAME_LEN);
            }
            const float mc = m * (1.0f - PREEMPH);

            for (int n = lane; n < FFT_LEN; n += 32) {
                float v = 0.0f;
                if (valid && n < FRAME_LEN) {
                    if (n == 0) v = (stage[o] * 32768.0f - m) * (1.0f - PREEMPH);
                    else        v = (stage[o + n] - PREEMPH * stage[o + n - 1]) * 32768.0f - mc;
                    v *= win_s[n];
                }
                dstf[PHYS8(n) * 2 + w] = v;
            }
        }
        GBAR();

        float vr[8], vi[8];

        // ---- pass 1: A -> B  (Ns=1)
        #pragma unroll
        for (int r = 0; r < 8; ++r) {
            float2 z = A[g][PHYS8(j + (r << 6))];
            vr[r] = z.x; vi[r] = z.y;
        }
        fft8(vr, vi);
        {
            const int d = j << 3;
            #pragma unroll
            for (int m = 0; m < 8; ++m)
                B[g][PHYS8(d + BRv[m])] = make_float2(vr[m], vi[m]);
        }
        GBAR();

        // ---- pass 2: B -> A  (Ns=8)
        {
            const int q = j & 7;
            #pragma unroll
            for (int r = 0; r < 8; ++r) {
                float2 z = B[g][PHYS8(j + (r << 6))];
                vr[r] = z.x; vi[r] = z.y;
                if (r) {
                    float2 wv = tw[(r * q) << 3];
                    CMUL(vr[r], vi[r], wv.x, wv.y);
                }
            }
            fft8(vr, vi);
            const int d = ((j >> 3) << 6) + (j & 7);
            #pragma unroll
            for (int m = 0; m < 8; ++m)
                A[g][PHYS8(d + (BRv[m] << 3))] = make_float2(vr[m], vi[m]);
        }
        GBAR();

        // ---- pass 3: A -> B  (Ns=64)
        {
            #pragma unroll
            for (int r = 0; r < 8; ++r) {
                float2 z = A[g][PHYS8(j + (r << 6))];
                vr[r] = z.x; vi[r] = z.y;
                if (r) {
                    float2 wv = tw[r * j];
                    CMUL(vr[r], vi[r], wv.x, wv.y);
                }
            }
            fft8(vr, vi);
            #pragma unroll
            for (int m = 0; m < 8; ++m)
                B[g][PHYS8(j + (BRv[m] << 6))] = make_float2(vr[m], vi[m]);
        }
        GBAR();

        // ---- unpack B -> power spectra into specg (A bytes); Z = A + iB
        for (int k = j; k < NBINS; k += 64) {
            const int mm = (FFT_LEN - k) & (FFT_LEN - 1);
            float2 z1 = B[g][PHYS8(k)];
            float2 z2 = B[g][PHYS8(mm)];
            float ar = z1.x + z2.x, ai = z1.y - z2.y;
            float br = z1.y + z2.y, bi = z1.x - z2.x;
            specg[k]           = 0.25f * (ar * ar + ai * ai);
            specg[SPEC_LD + k] = 0.25f * (br * br + bi * bi);
        }
        GBAR();

        // ---- sparse mel + log + stats: 160 tasks (2 frames x 80 bins) over 64 threads
        #pragma unroll
        for (int slot = 0; slot < 3; ++slot) {
            int t = j + slot * 64;
            if (t < 2 * NMEL) {
                int fr = (t >= NMEL) ? 1 : 0;
                int b  = t - fr * NMEL;
                int f2 = fg + fr;
                float lv = 0.0f;
                if (f2 < num_frames) {
                    int lo = klo_s[b], ww = wid_s[b], off = off_s[b];
                    float acc = 0.0f;
                    for (int i = 0; i < ww; ++i)
                        acc = fmaf(specg[fr * SPEC_LD + lo + i], wts_s[off + i], acc);
                    lv = logf(fmaxf(acc, MEL_FLOOR));
                    g_mel[(long long)f2 * NMEL + b] = lv;
                }
                acc_s[slot] += lv;
                acc_q[slot] += lv * lv;
            }
        }
        GBAR();    // protect specg(A)/stage(B) before next iteration
    }

    #pragma unroll
    for (int slot = 0; slot < 3; ++slot) {
        int a = blockIdx.x * PB + g * 192 + slot * 64 + j;
        g_psum[a] = acc_s[slot];
        g_psq [a] = acc_q[slot];
    }
}

// ---------------------------------------------------------------------------
// One block per mel bin; sum over (block i, group g, frame-parity fr).
__global__ void reduce2_kernel(int num_frames) {
    __shared__ double sh_s[256], sh_q[256];
    const int b = blockIdx.x;
    const int t = threadIdx.x;
    double s = 0.0, q = 0.0;
    for (int p = t; p < ABLOCKS * 8; p += 256) {
        int i  = p >> 3;
        int gg = (p >> 1) & 3;
        int fr = p & 1;
        int tk = fr * NMEL + b;               // task id within group
        int a  = i * PB + gg * 192 + (tk >> 6) * 64 + (tk & 63);
        s += (double)g_psum[a];
        q += (double)g_psq [a];
    }
    sh_s[t] = s; sh_q[t] = q;
    __syncthreads();
    #pragma unroll
    for (int o = 128; o > 0; o >>= 1) {
        if (t < o) { sh_s[t] += sh_s[t + o]; sh_q[t] += sh_q[t + o]; }
        __syncthreads();
    }
    if (t == 0) {
        double F = (double)num_frames;
        double mean = sh_s[0] / F;
        double var  = (sh_q[0] - F * mean * mean) / (F - 1.0);
        if (var < 0.0) var = 0.0;
        g_mean[b] = (float)mean;
        g_istd[b] = (float)(1.0 / sqrt(var + 1e-7));
    }
}

// ---------------------------------------------------------------------------
__global__ void normalize_kernel(float4* __restrict__ out, int n4) {
    __shared__ float mean_s[NMEL], istd_s[NMEL];
    if (threadIdx.x < NMEL) {
        mean_s[threadIdx.x] = g_mean[threadIdx.x];
        istd_s[threadIdx.x] = g_istd[threadIdx.x];
    }
    __syncthreads();
    const float4* mel4 = (const float4*)g_mel;
    for (int i = blockIdx.x * blockDim.x + threadIdx.x; i < n4;
         i += gridDim.x * blockDim.x) {
        int b = (i % 20) * 4;
        float4 v = mel4[i];
        float4 r;
        r.x = (v.x - mean_s[b    ]) * istd_s[b    ];
        r.y = (v.y - mean_s[b + 1]) * istd_s[b + 1];
        r.z = (v.z - mean_s[b + 2]) * istd_s[b + 2];
        r.w = (v.w - mean_s[b + 3]) * istd_s[b + 3];
        out[i] = r;
    }
}

// ---------------------------------------------------------------------------
extern "C" void kernel_launch(void* const* d_in, const int* in_sizes, int n_in,
                              void* d_out, int out_size) {
    const float* wav = (const float*)d_in[0];
    const float* fb  = (const float*)d_in[1];
    const float* win = (const float*)d_in[2];
    float* out = (float*)d_out;

    int T = in_sizes[0];
    int F = 1 + (T - FRAME_LEN) / HOP;
    if (F > MAX_FRAMES) F = MAX_FRAMES;

    const int dynB = 2 * 4 * BUF * 8;   // A + B float2[4][BUF] = 36864 B

    init_kernel<<<1, 512>>>(fb);
    fused_kernel<<<ABLOCKS, 256, dynB>>>(wav, win, F, T);
    reduce2_kernel<<<NMEL, 256>>>(F);
    normalize_kernel<<<1024, 256>>>((float4*)out, F * NMEL / 4);
}

// round 9
// speedup vs baseline: 1.2876x; 1.2466x over previous
#include <cuda_runtime.h>
#include <math.h>

#define FRAME_LEN 400
#define HOP 160
#define FFT_LEN 512
#define NBINS 257
#define NMEL 80
#define PREEMPH 0.97f
#define MEL_FLOOR 1.192092955078125e-07f
#define ABLOCKS 592
#define WCAP 640
#define PB 768               // per-block stat slots: 4 groups x 3 slots x 64

// ---- device scratch ----
#define MAX_FRAMES 60000
__device__ float  g_mel [MAX_FRAMES * NMEL];
__device__ float2 g_twid[512];
__device__ float  g_psum[ABLOCKS * PB];
__device__ float  g_psq [ABLOCKS * PB];
__device__ float  g_mean[NMEL];
__device__ float  g_istd[NMEL];
__device__ int    g_klo[NMEL];
__device__ int    g_wid[NMEL];
__device__ int    g_off[NMEL];
__device__ float  g_wts[WCAP];

// ---------------------------------------------------------------------------
// init (640 threads): twiddles + parallel filterbank compaction (8 lanes/bin).
__global__ void init_kernel(const float* __restrict__ fb) {
    __shared__ int lo_sh[NMEL], wid_sh[NMEL], off_sh[NMEL];
    const int tid = threadIdx.x;

    if (tid < 512) {
        double a = -2.0 * 3.14159265358979323846 * (double)tid / 512.0;
        g_twid[tid] = make_float2((float)cos(a), (float)sin(a));
    }

    const int b = tid >> 3;      // 0..79
    const int s = tid & 7;
    int lo = 512, hi = -1;
    for (int k = s; k < NBINS; k += 8) {
        if (fb[k * NMEL + b] != 0.0f) { lo = min(lo, k); hi = max(hi, k); }
    }
    #pragma unroll
    for (int o = 4; o > 0; o >>= 1) {
        lo = min(lo, __shfl_xor_sync(0xffffffffu, lo, o));
        hi = max(hi, __shfl_xor_sync(0xffffffffu, hi, o));
    }
    if (s == 0) {
        lo_sh[b]  = (hi >= lo) ? lo : 0;
        wid_sh[b] = (hi >= lo) ? (hi - lo + 1) : 0;
    }
    __syncthreads();
    if (tid == 0) {
        int off = 0;
        for (int i = 0; i < NMEL; ++i) {
            int w = wid_sh[i];
            if (off + w > WCAP) w = WCAP - off;
            if (w < 0) w = 0;
            wid_sh[i] = w;
            off_sh[i] = off;
            off += w;
        }
    }
    __syncthreads();
    if (tid < NMEL) {
        g_klo[tid] = lo_sh[tid];
        g_wid[tid] = wid_sh[tid];
        g_off[tid] = off_sh[tid];
    }
    {
        int off = off_sh[b], l0 = lo_sh[b], w = wid_sh[b];
        for (int i = s; i < w; i += 8)
            g_wts[off + i] = fb[(l0 + i) * NMEL + b];
    }
}

// ---------------------------------------------------------------------------
#define PHYS8(i) ((i) + ((i) >> 3))
#define BUF 576                 // float2 elems per group buffer
#define SPEC_LD 272
#define GSPAN 560               // HOP + FRAME_LEN (2-frame group span)

#define FFT2(ar,ai,br,bi) { float tr_=ar, ti_=ai; ar=tr_+br; ai=ti_+bi; br=tr_-br; bi=ti_-bi; }
#define CMUL(xr,xi,wr,wi) { float tr_=xr; xr=tr_*(wr)-xi*(wi); xi=tr_*(wi)+xi*(wr); }
#define RSQ2 0.70710678118654752440f
#define GBAR() asm volatile("bar.sync %0, 64;" :: "r"(1 + g) : "memory")

__device__ __forceinline__ void fft8(float* vr, float* vi) {
    FFT2(vr[0], vi[0], vr[4], vi[4]);
    FFT2(vr[1], vi[1], vr[5], vi[5]);
    FFT2(vr[2], vi[2], vr[6], vi[6]);
    FFT2(vr[3], vi[3], vr[7], vi[7]);
    CMUL(vr[5], vi[5],  RSQ2, -RSQ2);
    CMUL(vr[6], vi[6],  0.0f, -1.0f);
    CMUL(vr[7], vi[7], -RSQ2, -RSQ2);
    FFT2(vr[0], vi[0], vr[2], vi[2]);
    FFT2(vr[1], vi[1], vr[3], vi[3]);
    FFT2(vr[4], vi[4], vr[6], vi[6]);
    FFT2(vr[5], vi[5], vr[7], vi[7]);
    CMUL(vr[3], vi[3], 0.0f, -1.0f);
    CMUL(vr[7], vi[7], 0.0f, -1.0f);
    FFT2(vr[0], vi[0], vr[1], vi[1]);
    FFT2(vr[2], vi[2], vr[3], vi[3]);
    FFT2(vr[4], vi[4], vr[5], vi[5]);
    FFT2(vr[6], vi[6], vr[7], vi[7]);
}

__global__ __launch_bounds__(256, 4)
void fused_kernel(const float* __restrict__ wav,
                  const float* __restrict__ window,
                  int num_frames, int T) {
    extern __shared__ __align__(16) char dyn[];
    float2 (*A)[BUF] = (float2(*)[BUF])dyn;
    float2 (*B)[BUF] = (float2(*)[BUF])(dyn + 4 * BUF * 8);

    __shared__ float  win_s[FRAME_LEN];
    __shared__ float  wts_s[WCAP];
    __shared__ int    klo_s[NMEL], wid_s[NMEL], off_s[NMEL];

    const int tid  = threadIdx.x;
    const int g    = tid >> 6;      // independent 64-thread group
    const int j    = tid & 63;
    const int w    = j >> 5;        // local warp (0: re, 1: im)
    const int lane = j & 31;

    float* stage = (float*)&B[g][0];
    float* specg = (float*)&A[g][0];
    float* dstf  = (float*)&A[g][0];

    // per-thread twiddle bases (fixed across iterations)
    const float2 b2 = g_twid[(j & 7) << 3];   // W512^{8q}
    const float2 b3 = g_twid[j];              // W512^{j}

    for (int i = tid; i < FRAME_LEN; i += 256) win_s[i] = window[i];
    if (tid < NMEL) {
        klo_s[tid] = g_klo[tid];
        wid_s[tid] = g_wid[tid];
        off_s[tid] = g_off[tid];
    }
    __syncthreads();
    {
        int tot = off_s[NMEL - 1] + wid_s[NMEL - 1];
        for (int i = tid; i < tot; i += 256) wts_s[i] = g_wts[i];
    }
    __syncthreads();

    float acc_s[3] = {0.f, 0.f, 0.f};
    float acc_q[3] = {0.f, 0.f, 0.f};
    const int BRv[8] = {0, 4, 2, 6, 1, 5, 3, 7};

    for (int base = blockIdx.x * 8; base < num_frames; base += gridDim.x * 8) {
        const int  fg = base + 2 * g;
        const long long s0 = (long long)fg * HOP;

        // ---- phase 0: stage wav span (float4)
        for (int i = j * 4; i < GSPAN; i += 256) {
            float4 v;
            if (s0 + i + 3 < T) {
                v = *(const float4*)(wav + s0 + i);
            } else {
                v.x = (s0 + i     < T) ? wav[s0 + i]     : 0.0f;
                v.y = (s0 + i + 1 < T) ? wav[s0 + i + 1] : 0.0f;
                v.z = (s0 + i + 2 < T) ? wav[s0 + i + 2] : 0.0f;
                v.w = (s0 + i + 3 < T) ? wav[s0 + i + 3] : 0.0f;
            }
            *(float4*)&stage[i] = v;
        }
        GBAR();

        // ---- phase 1: mean + preemph + window; write only n < 400
        {
            const int  f     = fg + w;
            const bool valid = (f < num_frames);
            const int  o     = w * HOP;

            float m = 0.0f;
            if (valid) {
                float s = 0.0f;
                for (int n = lane; n < FRAME_LEN; n += 32) s += stage[o + n];
                #pragma unroll
                for (int t = 16; t > 0; t >>= 1) s += __shfl_xor_sync(0xffffffffu, s, t);
                m = s * (32768.0f / FRAME_LEN);
            }
            const float mc = m * (1.0f - PREEMPH);

            for (int n = lane; n < FRAME_LEN; n += 32) {
                float v = 0.0f;
                if (valid) {
                    if (n == 0) v = (stage[o] * 32768.0f - m) * (1.0f - PREEMPH);
                    else        v = (stage[o + n] - PREEMPH * stage[o + n - 1]) * 32768.0f - mc;
                    v *= win_s[n];
                }
                dstf[PHYS8(n) * 2 + w] = v;
            }
        }
        GBAR();

        float vr[8], vi[8];

        // ---- pass 1: A -> B  (Ns=1); indices >= 400 are implicit zeros
        #pragma unroll
        for (int r = 0; r < 6; ++r) {
            float2 z = A[g][PHYS8(j + (r << 6))];
            vr[r] = z.x; vi[r] = z.y;
        }
        if (j < 16) {              // n = 384+j < 400 only for j<16
            float2 z = A[g][PHYS8(j + 384)];
            vr[6] = z.x; vi[6] = z.y;
        } else { vr[6] = 0.0f; vi[6] = 0.0f; }
        vr[7] = 0.0f; vi[7] = 0.0f;
        fft8(vr, vi);
        {
            const int d = j << 3;
            #pragma unroll
            for (int m = 0; m < 8; ++m)
                B[g][PHYS8(d + BRv[m])] = make_float2(vr[m], vi[m]);
        }
        GBAR();

        // ---- pass 2: B -> A  (Ns=8); progressive register twiddles (W512^{8q})^r
        {
            float wr = 1.0f, wi = 0.0f;
            #pragma unroll
            for (int r = 0; r < 8; ++r) {
                float2 z = B[g][PHYS8(j + (r << 6))];
                vr[r] = z.x; vi[r] = z.y;
                if (r) {
                    CMUL(wr, wi, b2.x, b2.y);
                    CMUL(vr[r], vi[r], wr, wi);
                }
            }
            fft8(vr, vi);
            const int d = ((j >> 3) << 6) + (j & 7);
            #pragma unroll
            for (int m = 0; m < 8; ++m)
                A[g][PHYS8(d + (BRv[m] << 3))] = make_float2(vr[m], vi[m]);
        }
        GBAR();

        // ---- pass 3: A -> B  (Ns=64); progressive twiddles (W512^j)^r
        {
            float wr = 1.0f, wi = 0.0f;
            #pragma unroll
            for (int r = 0; r < 8; ++r) {
                float2 z = A[g][PHYS8(j + (r << 6))];
                vr[r] = z.x; vi[r] = z.y;
                if (r) {
                    CMUL(wr, wi, b3.x, b3.y);
                    CMUL(vr[r], vi[r], wr, wi);
                }
            }
            fft8(vr, vi);
            #pragma unroll
            for (int m = 0; m < 8; ++m)
                B[g][PHYS8(j + (BRv[m] << 6))] = make_float2(vr[m], vi[m]);
        }
        GBAR();

        // ---- unpack B -> power spectra into specg (A bytes); Z = A + iB
        for (int k = j; k < NBINS; k += 64) {
            const int mm = (FFT_LEN - k) & (FFT_LEN - 1);
            float2 z1 = B[g][PHYS8(k)];
            float2 z2 = B[g][PHYS8(mm)];
            float ar = z1.x + z2.x, ai = z1.y - z2.y;
            float br = z1.y + z2.y, bi = z1.x - z2.x;
            specg[k]           = 0.25f * (ar * ar + ai * ai);
            specg[SPEC_LD + k] = 0.25f * (br * br + bi * bi);
        }
        GBAR();

        // ---- sparse mel + log + stats: 160 tasks over 64 threads
        #pragma unroll
        for (int slot = 0; slot < 3; ++slot) {
            int t = j + slot * 64;
            if (t < 2 * NMEL) {
                int fr = (t >= NMEL) ? 1 : 0;
                int b  = t - fr * NMEL;
                int f2 = fg + fr;
                float lv = 0.0f;
                if (f2 < num_frames) {
                    int lo = klo_s[b], ww = wid_s[b], off = off_s[b];
                    float acc = 0.0f;
                    for (int i = 0; i < ww; ++i)
                        acc = fmaf(specg[fr * SPEC_LD + lo + i], wts_s[off + i], acc);
                    lv = logf(fmaxf(acc, MEL_FLOOR));
                    g_mel[(long long)f2 * NMEL + b] = lv;
                }
                acc_s[slot] += lv;
                acc_q[slot] += lv * lv;
            }
        }
        GBAR();
    }

    #pragma unroll
    for (int slot = 0; slot < 3; ++slot) {
        int a = blockIdx.x * PB + g * 192 + slot * 64 + j;
        g_psum[a] = acc_s[slot];
        g_psq [a] = acc_q[slot];
    }
}

// ---------------------------------------------------------------------------
__global__ void reduce2_kernel(int num_frames) {
    __shared__ double sh_s[256], sh_q[256];
    const int b = blockIdx.x;
    const int t = threadIdx.x;
    double s = 0.0, q = 0.0;
    for (int p = t; p < ABLOCKS * 8; p += 256) {
        int i  = p >> 3;
        int gg = (p >> 1) & 3;
        int fr = p & 1;
        int tk = fr * NMEL + b;
        int a  = i * PB + gg * 192 + (tk >> 6) * 64 + (tk & 63);
        s += (double)g_psum[a];
        q += (double)g_psq [a];
    }
    sh_s[t] = s; sh_q[t] = q;
    __syncthreads();
    #pragma unroll
    for (int o = 128; o > 0; o >>= 1) {
        if (t < o) { sh_s[t] += sh_s[t + o]; sh_q[t] += sh_q[t + o]; }
        __syncthreads();
    }
    if (t == 0) {
        double F = (double)num_frames;
        double mean = sh_s[0] / F;
        double var  = (sh_q[0] - F * mean * mean) / (F - 1.0);
        if (var < 0.0) var = 0.0;
        g_mean[b] = (float)mean;
        g_istd[b] = (float)(1.0 / sqrt(var + 1e-7));
    }
}

// ---------------------------------------------------------------------------
__global__ void normalize_kernel(float4* __restrict__ out, int n4) {
    __shared__ float mean_s[NMEL], istd_s[NMEL];
    if (threadIdx.x < NMEL) {
        mean_s[threadIdx.x] = g_mean[threadIdx.x];
        istd_s[threadIdx.x] = g_istd[threadIdx.x];
    }
    __syncthreads();
    const float4* mel4 = (const float4*)g_mel;
    const int stride = gridDim.x * blockDim.x;
    for (int i = blockIdx.x * blockDim.x + threadIdx.x; i < n4; i += 2 * stride) {
        const int i2 = i + stride;
        float4 v1 = mel4[i];
        float4 v2;
        const bool p2 = (i2 < n4);
        if (p2) v2 = mel4[i2];
        int b1 = (i % 20) * 4;
        float4 r1;
        r1.x = (v1.x - mean_s[b1    ]) * istd_s[b1    ];
        r1.y = (v1.y - mean_s[b1 + 1]) * istd_s[b1 + 1];
        r1.z = (v1.z - mean_s[b1 + 2]) * istd_s[b1 + 2];
        r1.w = (v1.w - mean_s[b1 + 3]) * istd_s[b1 + 3];
        out[i] = r1;
        if (p2) {
            int b2 = (i2 % 20) * 4;
            float4 r2;
            r2.x = (v2.x - mean_s[b2    ]) * istd_s[b2    ];
            r2.y = (v2.y - mean_s[b2 + 1]) * istd_s[b2 + 1];
            r2.z = (v2.z - mean_s[b2 + 2]) * istd_s[b2 + 2];
            r2.w = (v2.w - mean_s[b2 + 3]) * istd_s[b2 + 3];
            out[i2] = r2;
        }
    }
}

// ---------------------------------------------------------------------------
extern "C" void kernel_launch(void* const* d_in, const int* in_sizes, int n_in,
                              void* d_out, int out_size) {
    const float* wav = (const float*)d_in[0];
    const float* fb  = (const float*)d_in[1];
    const float* win = (const float*)d_in[2];
    float* out = (float*)d_out;

    int T = in_sizes[0];
    int F = 1 + (T - FRAME_LEN) / HOP;
    if (F > MAX_FRAMES) F = MAX_FRAMES;

    const int dynB = 2 * 4 * BUF * 8;   // A + B float2[4][BUF] = 36864 B

    init_kernel<<<1, 640>>>(fb);
    fused_kernel<<<ABLOCKS, 256, dynB>>>(wav, win, F, T);
    reduce2_kernel<<<NMEL, 256>>>(F);
    normalize_kernel<<<1024, 256>>>((float4*)out, F * NMEL / 4);
}

// round 10
// speedup vs baseline: 1.2879x; 1.0002x over previous
#include <cuda_runtime.h>
#include <math.h>

#define FRAME_LEN 400
#define HOP 160
#define FFT_LEN 512
#define NBINS 257
#define NMEL 80
#define PREEMPH 0.97f
#define MEL_FLOOR 1.192092955078125e-07f
#define ABLOCKS 592
#define WCAP 640
#define PB 768               // per-block stat slots: 4 groups x 3 slots x 64

// ---- device scratch ----
#define MAX_FRAMES 60000
__device__ float  g_mel [MAX_FRAMES * NMEL];
__device__ float2 g_twid[512];
__device__ float  g_psum[ABLOCKS * PB];
__device__ float  g_psq [ABLOCKS * PB];
__device__ float  g_mean[NMEL];
__device__ float  g_istd[NMEL];
__device__ int    g_klo[NMEL];
__device__ int    g_wid[NMEL];
__device__ int    g_off[NMEL];
__device__ float  g_wts[WCAP];

// ---------------------------------------------------------------------------
// init (640 threads): twiddles + parallel filterbank compaction (8 lanes/bin).
__global__ void init_kernel(const float* __restrict__ fb) {
    __shared__ int lo_sh[NMEL], wid_sh[NMEL], off_sh[NMEL];
    const int tid = threadIdx.x;

    if (tid < 512) {
        double a = -2.0 * 3.14159265358979323846 * (double)tid / 512.0;
        g_twid[tid] = make_float2((float)cos(a), (float)sin(a));
    }

    const int b = tid >> 3;      // 0..79
    const int s = tid & 7;
    int lo = 512, hi = -1;
    for (int k = s; k < NBINS; k += 8) {
        if (fb[k * NMEL + b] != 0.0f) { lo = min(lo, k); hi = max(hi, k); }
    }
    #pragma unroll
    for (int o = 4; o > 0; o >>= 1) {
        lo = min(lo, __shfl_xor_sync(0xffffffffu, lo, o));
        hi = max(hi, __shfl_xor_sync(0xffffffffu, hi, o));
    }
    if (s == 0) {
        lo_sh[b]  = (hi >= lo) ? lo : 0;
        wid_sh[b] = (hi >= lo) ? (hi - lo + 1) : 0;
    }
    __syncthreads();
    if (tid == 0) {
        int off = 0;
        for (int i = 0; i < NMEL; ++i) {
            int w = wid_sh[i];
            if (off + w > WCAP) w = WCAP - off;
            if (w < 0) w = 0;
            wid_sh[i] = w;
            off_sh[i] = off;
            off += w;
        }
    }
    __syncthreads();
    if (tid < NMEL) {
        g_klo[tid] = lo_sh[tid];
        g_wid[tid] = wid_sh[tid];
        g_off[tid] = off_sh[tid];
    }
    {
        int off = off_sh[b], l0 = lo_sh[b], w = wid_sh[b];
        for (int i = s; i < w; i += 8)
            g_wts[off + i] = fb[(l0 + i) * NMEL + b];
    }
}

// ---------------------------------------------------------------------------
#define PHYS8(i) ((i) + ((i) >> 3))
#define BUF 576                 // float2 elems per group buffer
#define SPEC_LD 272
#define GSPAN 560               // HOP + FRAME_LEN (2-frame group span)

#define FFT2(ar,ai,br,bi) { float tr_=ar, ti_=ai; ar=tr_+br; ai=ti_+bi; br=tr_-br; bi=ti_-bi; }
#define CMUL(xr,xi,wr,wi) { float tr_=xr; xr=tr_*(wr)-xi*(wi); xi=tr_*(wi)+xi*(wr); }
#define RSQ2 0.70710678118654752440f
#define GBAR() asm volatile("bar.sync %0, 64;" :: "r"(1 + g) : "memory")

__device__ __forceinline__ void fft8(float* vr, float* vi) {
    FFT2(vr[0], vi[0], vr[4], vi[4]);
    FFT2(vr[1], vi[1], vr[5], vi[5]);
    FFT2(vr[2], vi[2], vr[6], vi[6]);
    FFT2(vr[3], vi[3], vr[7], vi[7]);
    CMUL(vr[5], vi[5],  RSQ2, -RSQ2);
    CMUL(vr[6], vi[6],  0.0f, -1.0f);
    CMUL(vr[7], vi[7], -RSQ2, -RSQ2);
    FFT2(vr[0], vi[0], vr[2], vi[2]);
    FFT2(vr[1], vi[1], vr[3], vi[3]);
    FFT2(vr[4], vi[4], vr[6], vi[6]);
    FFT2(vr[5], vi[5], vr[7], vi[7]);
    CMUL(vr[3], vi[3], 0.0f, -1.0f);
    CMUL(vr[7], vi[7], 0.0f, -1.0f);
    FFT2(vr[0], vi[0], vr[1], vi[1]);
    FFT2(vr[2], vi[2], vr[3], vi[3]);
    FFT2(vr[4], vi[4], vr[5], vi[5]);
    FFT2(vr[6], vi[6], vr[7], vi[7]);
}

__global__ __launch_bounds__(256, 4)
void fused_kernel(const float* __restrict__ wav,
                  const float* __restrict__ window,
                  int num_frames, int T) {
    extern __shared__ __align__(16) char dyn[];
    float2 (*A)[BUF] = (float2(*)[BUF])dyn;
    float2 (*B)[BUF] = (float2(*)[BUF])(dyn + 4 * BUF * 8);

    __shared__ float  wts_s[WCAP];
    __shared__ int    klo_s[NMEL], wid_s[NMEL], off_s[NMEL];

    const int tid  = threadIdx.x;
    const int g    = tid >> 6;      // independent 64-thread group
    const int j    = tid & 63;
    const int w    = j >> 5;        // local warp (0: re, 1: im)
    const int lane = j & 31;

    float* stage = (float*)&B[g][0];
    float* specg = (float*)&A[g][0];
    float* dstf  = (float*)&A[g][0];

    // per-thread twiddle bases (fixed across iterations)
    const float2 b2 = g_twid[(j & 7) << 3];   // W512^{8q}
    const float2 b3 = g_twid[j];              // W512^{j}

    // window cached in registers: indices lane + 32*i are thread-fixed
    float win_r[13];
    #pragma unroll
    for (int i = 0; i < 13; ++i) {
        int n = lane + 32 * i;
        win_r[i] = (n < FRAME_LEN) ? window[n] : 0.0f;
    }

    if (tid < NMEL) {
        klo_s[tid] = g_klo[tid];
        wid_s[tid] = g_wid[tid];
        off_s[tid] = g_off[tid];
    }
    __syncthreads();
    {
        int tot = off_s[NMEL - 1] + wid_s[NMEL - 1];
        for (int i = tid; i < tot; i += 256) wts_s[i] = g_wts[i];
    }
    __syncthreads();

    float acc_s[3] = {0.f, 0.f, 0.f};
    float acc_q[3] = {0.f, 0.f, 0.f};
    const int BRv[8] = {0, 4, 2, 6, 1, 5, 3, 7};

    for (int base = blockIdx.x * 8; base < num_frames; base += gridDim.x * 8) {
        const int  fg = base + 2 * g;
        const long long s0 = (long long)fg * HOP;

        // ---- phase 0: stage wav span (float4)
        for (int i = j * 4; i < GSPAN; i += 256) {
            float4 v;
            if (s0 + i + 3 < T) {
                v = *(const float4*)(wav + s0 + i);
            } else {
                v.x = (s0 + i     < T) ? wav[s0 + i]     : 0.0f;
                v.y = (s0 + i + 1 < T) ? wav[s0 + i + 1] : 0.0f;
                v.z = (s0 + i + 2 < T) ? wav[s0 + i + 2] : 0.0f;
                v.w = (s0 + i + 3 < T) ? wav[s0 + i + 3] : 0.0f;
            }
            *(float4*)&stage[i] = v;
        }
        GBAR();   // also orders prior-iteration mel A-reads before phase-1 A-writes

        // ---- phase 1: mean + preemph + window; frame values cached in regs
        {
            const int  f     = fg + w;
            const bool valid = (f < num_frames);
            const int  o     = w * HOP;

            float xv[13];
            float s = 0.0f;
            #pragma unroll
            for (int i = 0; i < 13; ++i) {
                int n = lane + 32 * i;
                xv[i] = (n < FRAME_LEN) ? stage[o + n] : 0.0f;
                s += xv[i];
            }
            #pragma unroll
            for (int t = 16; t > 0; t >>= 1) s += __shfl_xor_sync(0xffffffffu, s, t);
            const float m  = valid ? s * (32768.0f / FRAME_LEN) : 0.0f;
            const float mc = m * (1.0f - PREEMPH);

            #pragma unroll
            for (int i = 0; i < 13; ++i) {
                int n = lane + 32 * i;
                if (n < FRAME_LEN) {
                    float v = 0.0f;
                    if (valid) {
                        if (n == 0) v = (xv[0] * 32768.0f - m) * (1.0f - PREEMPH);
                        else        v = (xv[i] - PREEMPH * stage[o + n - 1]) * 32768.0f - mc;
                        v *= win_r[i];
                    }
                    dstf[PHYS8(n) * 2 + w] = v;
                }
            }
        }
        GBAR();

        float vr[8], vi[8];

        // ---- pass 1: A -> B  (Ns=1); indices >= 400 are implicit zeros
        #pragma unroll
        for (int r = 0; r < 6; ++r) {
            float2 z = A[g][PHYS8(j + (r << 6))];
            vr[r] = z.x; vi[r] = z.y;
        }
        if (j < 16) {
            float2 z = A[g][PHYS8(j + 384)];
            vr[6] = z.x; vi[6] = z.y;
        } else { vr[6] = 0.0f; vi[6] = 0.0f; }
        vr[7] = 0.0f; vi[7] = 0.0f;
        fft8(vr, vi);
        {
            const int d = j << 3;
            #pragma unroll
            for (int m = 0; m < 8; ++m)
                B[g][PHYS8(d + BRv[m])] = make_float2(vr[m], vi[m]);
        }
        GBAR();

        // ---- pass 2: B -> A  (Ns=8); progressive register twiddles
        {
            float wr = 1.0f, wi = 0.0f;
            #pragma unroll
            for (int r = 0; r < 8; ++r) {
                float2 z = B[g][PHYS8(j + (r << 6))];
                vr[r] = z.x; vi[r] = z.y;
                if (r) {
                    CMUL(wr, wi, b2.x, b2.y);
                    CMUL(vr[r], vi[r], wr, wi);
                }
            }
            fft8(vr, vi);
            const int d = ((j >> 3) << 6) + (j & 7);
            #pragma unroll
            for (int m = 0; m < 8; ++m)
                A[g][PHYS8(d + (BRv[m] << 3))] = make_float2(vr[m], vi[m]);
        }
        GBAR();

        // ---- pass 3: A -> B  (Ns=64); progressive twiddles
        {
            float wr = 1.0f, wi = 0.0f;
            #pragma unroll
            for (int r = 0; r < 8; ++r) {
                float2 z = A[g][PHYS8(j + (r << 6))];
                vr[r] = z.x; vi[r] = z.y;
                if (r) {
                    CMUL(wr, wi, b3.x, b3.y);
                    CMUL(vr[r], vi[r], wr, wi);
                }
            }
            fft8(vr, vi);
            #pragma unroll
            for (int m = 0; m < 8; ++m)
                B[g][PHYS8(j + (BRv[m] << 6))] = make_float2(vr[m], vi[m]);
        }
        GBAR();

        // ---- unpack B -> power spectra into specg (A bytes); Z = A + iB
        for (int k = j; k < NBINS; k += 64) {
            const int mm = (FFT_LEN - k) & (FFT_LEN - 1);
            float2 z1 = B[g][PHYS8(k)];
            float2 z2 = B[g][PHYS8(mm)];
            float ar = z1.x + z2.x, ai = z1.y - z2.y;
            float br = z1.y + z2.y, bi = z1.x - z2.x;
            specg[k]           = 0.25f * (ar * ar + ai * ai);
            specg[SPEC_LD + k] = 0.25f * (br * br + bi * bi);
        }
        GBAR();

        // ---- sparse mel + log + stats: 160 tasks over 64 threads
        #pragma unroll
        for (int slot = 0; slot < 3; ++slot) {
            int t = j + slot * 64;
            if (t < 2 * NMEL) {
                int fr = (t >= NMEL) ? 1 : 0;
                int b  = t - fr * NMEL;
                int f2 = fg + fr;
                float lv = 0.0f;
                if (f2 < num_frames) {
                    int lo = klo_s[b], ww = wid_s[b], off = off_s[b];
                    float acc = 0.0f;
                    for (int i = 0; i < ww; ++i)
                        acc = fmaf(specg[fr * SPEC_LD + lo + i], wts_s[off + i], acc);
                    lv = logf(fmaxf(acc, MEL_FLOOR));
                    g_mel[(long long)f2 * NMEL + b] = lv;
                }
                acc_s[slot] += lv;
                acc_q[slot] += lv * lv;
            }
        }
        // no end barrier: phase-0 GBAR of the next iteration provides the ordering
    }

    #pragma unroll
    for (int slot = 0; slot < 3; ++slot) {
        int a = blockIdx.x * PB + g * 192 + slot * 64 + j;
        g_psum[a] = acc_s[slot];
        g_psq [a] = acc_q[slot];
    }
}

// ---------------------------------------------------------------------------
__global__ void reduce2_kernel(int num_frames) {
    __shared__ double sh_s[256], sh_q[256];
    const int b = blockIdx.x;
    const int t = threadIdx.x;
    double s = 0.0, q = 0.0;
    for (int p = t; p < ABLOCKS * 8; p += 256) {
        int i  = p >> 3;
        int gg = (p >> 1) & 3;
        int fr = p & 1;
        int tk = fr * NMEL + b;
        int a  = i * PB + gg * 192 + (tk >> 6) * 64 + (tk & 63);
        s += (double)g_psum[a];
        q += (double)g_psq [a];
    }
    sh_s[t] = s; sh_q[t] = q;
    __syncthreads();
    #pragma unroll
    for (int o = 128; o > 0; o >>= 1) {
        if (t < o) { sh_s[t] += sh_s[t + o]; sh_q[t] += sh_q[t + o]; }
        __syncthreads();
    }
    if (t == 0) {
        double F = (double)num_frames;
        double mean = sh_s[0] / F;
        double var  = (sh_q[0] - F * mean * mean) / (F - 1.0);
        if (var < 0.0) var = 0.0;
        g_mean[b] = (float)mean;
        g_istd[b] = (float)(1.0 / sqrt(var + 1e-7));
    }
}

// ---------------------------------------------------------------------------
__global__ void normalize_kernel(float4* __restrict__ out, int n4) {
    __shared__ float mean_s[NMEL], istd_s[NMEL];
    if (threadIdx.x < NMEL) {
        mean_s[threadIdx.x] = g_mean[threadIdx.x];
        istd_s[threadIdx.x] = g_istd[threadIdx.x];
    }
    __syncthreads();
    const float4* mel4 = (const float4*)g_mel;
    const int stride = gridDim.x * blockDim.x;
    for (int i = blockIdx.x * blockDim.x + threadIdx.x; i < n4; i += 2 * stride) {
        const int i2 = i + stride;
        float4 v1 = mel4[i];
        float4 v2;
        const bool p2 = (i2 < n4);
        if (p2) v2 = mel4[i2];
        int b1 = (i % 20) * 4;
        float4 r1;
        r1.x = (v1.x - mean_s[b1    ]) * istd_s[b1    ];
        r1.y = (v1.y - mean_s[b1 + 1]) * istd_s[b1 + 1];
        r1.z = (v1.z - mean_s[b1 + 2]) * istd_s[b1 + 2];
        r1.w = (v1.w - mean_s[b1 + 3]) * istd_s[b1 + 3];
        out[i] = r1;
        if (p2) {
            int b2 = (i2 % 20) * 4;
            float4 r2;
            r2.x = (v2.x - mean_s[b2    ]) * istd_s[b2    ];
            r2.y = (v2.y - mean_s[b2 + 1]) * istd_s[b2 + 1];
            r2.z = (v2.z - mean_s[b2 + 2]) * istd_s[b2 + 2];
            r2.w = (v2.w - mean_s[b2 + 3]) * istd_s[b2 + 3];
            out[i2] = r2;
        }
    }
}

// ---------------------------------------------------------------------------
extern "C" void kernel_launch(void* const* d_in, const int* in_sizes, int n_in,
                              void* d_out, int out_size) {
    const float* wav = (const float*)d_in[0];
    const float* fb  = (const float*)d_in[1];
    const float* win = (const float*)d_in[2];
    float* out = (float*)d_out;

    int T = in_sizes[0];
    int F = 1 + (T - FRAME_LEN) / HOP;
    if (F > MAX_FRAMES) F = MAX_FRAMES;

    const int dynB = 2 * 4 * BUF * 8;   // A + B float2[4][BUF] = 36864 B

    init_kernel<<<1, 640>>>(fb);
    fused_kernel<<<ABLOCKS, 256, dynB>>>(wav, win, F, T);
    reduce2_kernel<<<NMEL, 256>>>(F);
    normalize_kernel<<<2048, 256>>>((float4*)out, F * NMEL / 4);
}